// round 1
// baseline (speedup 1.0000x reference)
#include <cuda_runtime.h>
#include <math.h>

#define BATCH   2
#define SEQLEN  2048
#define DMODEL  512
#define DSTATE  64
#define TILE    32

// One warp handles one (b, h) channel. Each lane owns 2 of the 64 states.
// z_n(t) = a_n z_n(t-1) + u(t)   (b folded into c: c_n = C_n * B_d_n)
// y(t)   = sum_n c_n z_n(t) + D_h u(t)
__global__ __launch_bounds__(128, 8)
void s4_scan_kernel(const float* __restrict__ u,
                    const float* __restrict__ B_re,
                    const float* __restrict__ C_re,
                    const float* __restrict__ log_dt,
                    const float* __restrict__ Dp,
                    float* __restrict__ y)
{
    const int warp = blockIdx.x * (blockDim.x >> 5) + (threadIdx.x >> 5);
    const int lane = threadIdx.x & 31;
    const int b = warp >> 9;            // / 512
    const int h = warp & 511;

    const int n0 = lane * 2;
    const int n1 = n0 + 1;

    // Per-(h,n) coefficients, computed once in double precision.
    const double delta = exp((double)log_dt[h]);
    const double A0 = exp(-0.5 * log1p((double)(n0 + 1) / (double)DSTATE));
    const double A1 = exp(-0.5 * log1p((double)(n1 + 1) / (double)DSTATE));
    const float a0 = (float)exp(delta * A0);
    const float a1 = (float)exp(delta * A1);
    const double bd0 = expm1(delta * A0) * (double)B_re[n0] * delta;
    const double bd1 = expm1(delta * A1) * (double)B_re[n1] * delta;
    const float c0 = (float)((double)C_re[n0] * bd0);
    const float c1 = (float)((double)C_re[n1] * bd1);
    const float Dh = Dp[h];

    const float* ub = u + (size_t)b * SEQLEN * DMODEL + h;
    float*       yb = y + (size_t)b * SEQLEN * DMODEL + h;

    float z0 = 0.0f, z1 = 0.0f;

    // lane l holds u(t0 + l) for the current tile; prefetch next tile.
    float ucur = ub[(size_t)lane * DMODEL];

    for (int tile = 0; tile < SEQLEN / TILE; ++tile) {
        const int t0 = tile * TILE;
        float unext = 0.0f;
        if (tile + 1 < SEQLEN / TILE)
            unext = ub[(size_t)(t0 + TILE + lane) * DMODEL];

        float p[TILE];
#pragma unroll
        for (int s = 0; s < TILE; ++s) {
            const float ut = __shfl_sync(0xffffffffu, ucur, s);
            z0 = fmaf(a0, z0, ut);
            z1 = fmaf(a1, z1, ut);
            p[s] = fmaf(c1, z1, c0 * z0);   // this lane's 2-state contribution at time t0+s
        }

        // Transpose-reduction over lanes: 31 shfls per 32 timesteps.
        // After stage m, p[j] (j < m) holds partial sums for timesteps whose
        // bit log2(m) matches the lane's bit; final p[0] = y_ssm(t0 + lane).
#pragma unroll
        for (int m = 16; m >= 1; m >>= 1) {
#pragma unroll
            for (int j = 0; j < m; ++j) {
                const bool hi = (lane & m) != 0;
                const float mine = hi ? p[m + j] : p[j];
                const float oth  = hi ? p[j]     : p[m + j];
                const float rec  = __shfl_xor_sync(0xffffffffu, oth, m);
                p[j] = mine + rec;
            }
        }

        // lane l writes y at t = t0 + l (its own ucur is u at that t).
        yb[(size_t)(t0 + lane) * DMODEL] = p[0] + Dh * ucur;

        ucur = unext;
    }
}

extern "C" void kernel_launch(void* const* d_in, const int* in_sizes, int n_in,
                              void* d_out, int out_size)
{
    const float* u      = (const float*)d_in[0];
    const float* B_re   = (const float*)d_in[1];
    const float* C_re   = (const float*)d_in[2];
    const float* log_dt = (const float*)d_in[3];
    const float* Dp     = (const float*)d_in[4];
    float* y = (float*)d_out;

    // 1024 warps total (one per (b,h)); 4 warps per block.
    const int threads = 128;
    const int blocks  = (BATCH * DMODEL) / (threads / 32);
    s4_scan_kernel<<<blocks, threads>>>(u, B_re, C_re, log_dt, Dp, y);
}